// round 1
// baseline (speedup 1.0000x reference)
#include <cuda_runtime.h>

#define NSTEP 51200
#define BATCH 512

// ---------------- scratch (static device arrays; no allocation) ----------------
__device__ float g_xproj[NSTEP * 40];
__device__ float g_hseq [NSTEP * 10];
__device__ float g_xin1 [NSTEP * 20];   // conv_out (LSTM -> sc matmul)
__device__ float g_hl   [NSTEP * 60];   // 3-tau LIF spikes (reused hr1/hr2)
__device__ float g_c    [NSTEP * 20];   // einsum conv output (reused)
__device__ float g_s4   [NSTEP * 20];   // LIF4 spikes (reused)
__device__ float g_out1 [NSTEP * 20];
__device__ float g_out2 [NSTEP * 10];
__device__ float g_sfin [NSTEP * 10];
__device__ float g_fused[BATCH * 200];
__device__ float g_part [BATCH * 2];
__device__ float g_stats[3];

__device__ __forceinline__ float sigf(float x)  { return __fdividef(1.f, 1.f + __expf(-x)); }
__device__ __forceinline__ float tfast(float x) { return __fdividef(2.f, 1.f + __expf(-2.f * x)) - 1.f; }

// ---------------- K1: LSTM input projection xproj[r,j] = x_r . Wih[j] + bih[j]+bhh[j] ----
__global__ void k_xproj(const float* __restrict__ x, const float* __restrict__ wih,
                        const float* __restrict__ bih, const float* __restrict__ bhh) {
    __shared__ float xs[64 * 100];
    __shared__ float ws[40 * 65];     // padded stride 65 to kill bank conflicts
    __shared__ float bs[40];
    int b = blockIdx.x, tid = threadIdx.x;
    const float* xg = x + b * 6400;   // x[b, c, t'] contiguous as c*100+t'
    for (int i = tid; i < 6400; i += 256) xs[i] = xg[i];
    for (int i = tid; i < 2560; i += 256) ws[(i >> 6) * 65 + (i & 63)] = wih[i];
    if (tid < 40) bs[tid] = bih[tid] + bhh[tid];
    __syncthreads();
    for (int i = tid; i < 4000; i += 256) {
        int tp = i / 40, j = i % 40;
        float acc = bs[j];
        #pragma unroll
        for (int c0 = 0; c0 < 64; c0++)
            acc = fmaf(xs[c0 * 100 + tp], ws[j * 65 + c0], acc);
        g_xproj[(b * 100 + tp) * 40 + j] = acc;
    }
}

// ---------------- K2: serial LSTM scan, single warp ----------------
__global__ void k_lstm(const float* __restrict__ whh) {
    int lane = threadIdx.x;
    int k = lane < 10 ? lane : 0;
    float wi[10], wf[10], wg[10], wo[10];
    #pragma unroll
    for (int m = 0; m < 10; m++) {
        wi[m] = whh[k * 10 + m];         wf[m] = whh[(k + 10) * 10 + m];
        wg[m] = whh[(k + 20) * 10 + m];  wo[m] = whh[(k + 30) * 10 + m];
    }
    float h[10];
    #pragma unroll
    for (int m = 0; m < 10; m++) h[m] = 0.f;
    float c = 0.f;
    float A[4], B[4], C[4];
    const float* xp = g_xproj;

#define LOAD4(S, t) { const float* p = xp + (t) * 40 + k; \
    S[0] = p[0]; S[1] = p[10]; S[2] = p[20]; S[3] = p[30]; }

#define STEP(S, P, t) { int tl = (t) + 2; if (tl > NSTEP - 1) tl = NSTEP - 1; LOAD4(P, tl); \
    float ai = S[0], af = S[1], ag = S[2], ao = S[3]; \
    _Pragma("unroll") \
    for (int m = 0; m < 10; m++) { \
        ai = fmaf(wi[m], h[m], ai); af = fmaf(wf[m], h[m], af); \
        ag = fmaf(wg[m], h[m], ag); ao = fmaf(wo[m], h[m], ao); } \
    float tg = tfast(ag); \
    c = fmaf(sigf(af), c, sigf(ai) * tg); \
    float hk = sigf(ao) * tfast(c); \
    if (lane < 10) g_hseq[(t) * 10 + lane] = hk; \
    _Pragma("unroll") \
    for (int m = 0; m < 10; m++) h[m] = __shfl_sync(0xffffffffu, hk, m); }

    LOAD4(A, 0); LOAD4(B, 1);
    int t = 0;
    for (int it = 0; it < 17066; ++it) {   // 3*17066 = 51198 steps
        STEP(A, C, t); t++;
        STEP(B, A, t); t++;
        STEP(C, B, t); t++;
    }
    STEP(A, C, t); t++;
    STEP(B, A, t);
#undef STEP
#undef LOAD4
}

// ---------------- K3: conv_out = hseq @ sc_w[:,0,:].T + sc_b ----------------
__global__ void k_sc(const float* __restrict__ scw, const float* __restrict__ scb) {
    int i = blockIdx.x * 256 + threadIdx.x;
    if (i >= NSTEP * 20) return;
    int r = i / 20, o = i % 20;
    float acc = scb[o];
    const float* hr = g_hseq + r * 10;
    const float* w  = scw + o * 10;
    #pragma unroll
    for (int m = 0; m < 10; m++) acc = fmaf(hr[m], w[m], acc);
    g_xin1[i] = acc;
}

// ---------------- K4: 3-tau LIF scan (60 independent element chains) ----------------
__global__ void k_lif3(int sel) {
    int l = threadIdx.x;
    if (l >= 60) return;
    int kk = l / 20, f = l % 20;
    const float* in = sel ? g_out1 : g_xin1;
    float tau = (kk == 0) ? 1.2231301601484298f
              : (kk == 1) ? 1.3678794411714423f : 1.4493289641172216f;
    float th  = (kk == 0) ? 0.14f : (kk == 1) ? 0.08f : 0.06f;
    float invt = 1.0f / tau;
    float v = 0.f;
    float xb[16];
    #pragma unroll
    for (int i = 0; i < 16; i++) xb[i] = in[i * 20 + f];
    for (int t = 0; t < NSTEP; t += 16) {
        #pragma unroll
        for (int u = 0; u < 16; u++) {
            float xv = xb[u];
            int tn = t + u + 16;
            xb[u] = (tn < NSTEP) ? in[tn * 20 + f] : 0.f;
            float vn = fmaf(xv - v, invt, v);
            int msk = __float_as_int(vn - th) >> 31;      // all-ones if keep (vn<th)
            g_hl[(t + u) * 60 + f * 3 + kk] = __int_as_float(~msk & 0x3f800000);
            v = __int_as_float(__float_as_int(vn) & msk);
        }
    }
}

// ---------------- K5: c[t,o] = sum_{f,k} hl[t,f,k]*conv_w[o,f,k] + b[o] ----------------
__global__ void k_conv(const float* __restrict__ cw, const float* __restrict__ cb) {
    int i = blockIdx.x * 256 + threadIdx.x;
    if (i >= NSTEP * 20) return;
    int r = i / 20, o = i % 20;
    float acc = cb[o];
    const float* h0 = g_hl + r * 60;
    const float* w  = cw + o * 60;
    #pragma unroll
    for (int m = 0; m < 60; m++) acc = fmaf(h0[m], w[m], acc);
    g_c[i] = acc;
}

// ---------------- K6: single-tau LIF scan (20 chains) ----------------
__global__ void k_lif4() {
    int f = threadIdx.x;
    if (f >= 20) return;
    const float invt = 1.0f / 1.3678794411714423f;
    const float th = 0.08f;
    float v = 0.f;
    float xb[16];
    #pragma unroll
    for (int i = 0; i < 16; i++) xb[i] = g_c[i * 20 + f];
    for (int t = 0; t < NSTEP; t += 16) {
        #pragma unroll
        for (int u = 0; u < 16; u++) {
            float xv = xb[u];
            int tn = t + u + 16;
            xb[u] = (tn < NSTEP) ? g_c[tn * 20 + f] : 0.f;
            float vn = fmaf(xv - v, invt, v);
            int msk = __float_as_int(vn - th) >> 31;
            g_s4[(t + u) * 20 + f] = __int_as_float(~msk & 0x3f800000);
            v = __int_as_float(__float_as_int(vn) & msk);
        }
    }
}

// ---------------- K7: out = s4 @ fc.T + fc_b + xin @ skip.T + skip_b ----------------
__global__ void k_fcskip(const float* __restrict__ fcw, const float* __restrict__ fcb,
                         const float* __restrict__ skw, const float* __restrict__ skb,
                         int which) {
    int Fout = which ? 10 : 20;
    int i = blockIdx.x * 256 + threadIdx.x;
    if (i >= NSTEP * Fout) return;
    int r = i / Fout, o = i % Fout;
    const float* xin = which ? g_out1 : g_xin1;
    float* out       = which ? g_out2 : g_out1;
    float acc = fcb[o] + skb[o];
    const float* s  = g_s4 + r * 20;
    const float* xr = xin + r * 20;
    const float* w1 = fcw + o * 20;
    const float* w2 = skw + o * 20;
    #pragma unroll
    for (int m = 0; m < 20; m++)
        acc = fmaf(s[m], w1[m], fmaf(xr[m], w2[m], acc));
    out[i] = acc;
}

// ---------------- K8: final LIF over the batch axis (512 steps, 1000 chains) ----------------
__global__ void k_liff() {
    int idx = threadIdx.x;
    if (idx >= 1000) return;
    const float invt = 1.0f / 1.3678794411714423f;
    const float th = 0.08f;
    float v = 0.f;
    float xb[8];
    #pragma unroll
    for (int i = 0; i < 8; i++) xb[i] = g_out2[i * 1000 + idx];
    for (int b = 0; b < BATCH; b += 8) {
        #pragma unroll
        for (int u = 0; u < 8; u++) {
            float xv = xb[u];
            int nb = b + u + 8;
            xb[u] = (nb < BATCH) ? g_out2[nb * 1000 + idx] : 0.f;
            float vn = fmaf(xv - v, invt, v);
            int msk = __float_as_int(vn - th) >> 31;
            g_sfin[(b + u) * 1000 + idx] = __int_as_float(~msk & 0x3f800000);
            v = __int_as_float(__float_as_int(vn) & msk);
        }
    }
}

// ---------------- K9: dp / avg / fused + per-batch partial sums ----------------
__global__ void k_fused() {
    int b = blockIdx.x, m = threadIdx.x;   // 32 threads, m<20 active
    float dp[10];
    float s1 = 0.f, s2 = 0.f;
    if (m < 20) {
        const float* sb = g_sfin + b * 1000;   // sb[t'*10 + j]
        float avgm = 0.f;
        #pragma unroll
        for (int j = 0; j < 10; j++) {
            float a = sb[(5 * m + 3) * 10 + j] + sb[(5 * m + 4) * 10 + j]
                    - sb[(5 * m + 0) * 10 + j] - sb[(5 * m + 1) * 10 + j];
            dp[j] = 0.5f * a;
            avgm += dp[j];
        }
        avgm *= 0.1f;
        #pragma unroll
        for (int j = 0; j < 10; j++) {
            float fv = dp[j] * avgm;
            g_fused[b * 200 + j * 20 + m] = fv;
            s1 += fv; s2 += fv * fv;
        }
    }
    #pragma unroll
    for (int off = 16; off; off >>= 1) {
        s1 += __shfl_xor_sync(0xffffffffu, s1, off);
        s2 += __shfl_xor_sync(0xffffffffu, s2, off);
    }
    if (m == 0) { g_part[b * 2] = s1; g_part[b * 2 + 1] = s2; }
}

// ---------------- K10: deterministic global mean/var reduction ----------------
__global__ void k_stats(const float* __restrict__ gamma, const float* __restrict__ beta) {
    int l = threadIdx.x;
    float s1 = 0.f, s2 = 0.f;
    for (int i = l; i < BATCH; i += 32) { s1 += g_part[2 * i]; s2 += g_part[2 * i + 1]; }
    #pragma unroll
    for (int off = 16; off; off >>= 1) {
        s1 += __shfl_xor_sync(0xffffffffu, s1, off);
        s2 += __shfl_xor_sync(0xffffffffu, s2, off);
    }
    if (l == 0) {
        float n = (float)(BATCH * 200);
        float mean = s1 / n;
        float var = s2 / n - mean * mean;
        float rstd = 1.f / sqrtf(var + 1e-5f);
        g_stats[0] = mean; g_stats[1] = rstd * gamma[0]; g_stats[2] = beta[0];
    }
}

// ---------------- K11: BN + classifier + log_softmax ----------------
__global__ void k_logits(const float* __restrict__ clsw, const float* __restrict__ clsb,
                         float* __restrict__ out) {
    int b = blockIdx.x, l = threadIdx.x;
    float mean = g_stats[0], ga = g_stats[1], be = g_stats[2];
    float a0 = 0.f, a1 = 0.f, a2 = 0.f;
    for (int n = l; n < 200; n += 32) {
        float bn = (g_fused[b * 200 + n] - mean) * ga + be;
        a0 = fmaf(bn, clsw[n], a0);
        a1 = fmaf(bn, clsw[200 + n], a1);
        a2 = fmaf(bn, clsw[400 + n], a2);
    }
    #pragma unroll
    for (int off = 16; off; off >>= 1) {
        a0 += __shfl_xor_sync(0xffffffffu, a0, off);
        a1 += __shfl_xor_sync(0xffffffffu, a1, off);
        a2 += __shfl_xor_sync(0xffffffffu, a2, off);
    }
    if (l == 0) {
        float l0 = a0 + clsb[0], l1 = a1 + clsb[1], l2 = a2 + clsb[2];
        float mx = fmaxf(l0, fmaxf(l1, l2));
        float e0 = expf(l0 - mx), e1 = expf(l1 - mx), e2 = expf(l2 - mx);
        float lse = logf(e0 + e1 + e2) + mx;
        out[b * 3 + 0] = l0 - lse;
        out[b * 3 + 1] = l1 - lse;
        out[b * 3 + 2] = l2 - lse;
    }
}

// ---------------- launch ----------------
extern "C" void kernel_launch(void* const* d_in, const int* in_sizes, int n_in,
                              void* d_out, int out_size) {
    const float* x   = (const float*)d_in[0];
    const float* wih = (const float*)d_in[1];
    const float* whh = (const float*)d_in[2];
    const float* bih = (const float*)d_in[3];
    const float* bhh = (const float*)d_in[4];
    const float* scw = (const float*)d_in[5];
    const float* scb = (const float*)d_in[6];
    const float* c1w = (const float*)d_in[7];
    const float* c1b = (const float*)d_in[8];
    const float* f1w = (const float*)d_in[9];
    const float* f1b = (const float*)d_in[10];
    const float* s1w = (const float*)d_in[11];
    const float* s1b = (const float*)d_in[12];
    const float* c2w = (const float*)d_in[13];
    const float* c2b = (const float*)d_in[14];
    const float* f2w = (const float*)d_in[15];
    const float* f2b = (const float*)d_in[16];
    const float* s2w = (const float*)d_in[17];
    const float* s2b = (const float*)d_in[18];
    const float* gam = (const float*)d_in[19];
    const float* bet = (const float*)d_in[20];
    const float* clw = (const float*)d_in[21];
    const float* clb = (const float*)d_in[22];
    float* out = (float*)d_out;

    k_xproj <<<512, 256>>>(x, wih, bih, bhh);
    k_lstm  <<<1, 32>>>(whh);
    k_sc    <<<4000, 256>>>(scw, scb);
    k_lif3  <<<1, 64>>>(0);
    k_conv  <<<4000, 256>>>(c1w, c1b);
    k_lif4  <<<1, 32>>>();
    k_fcskip<<<4000, 256>>>(f1w, f1b, s1w, s1b, 0);
    k_lif3  <<<1, 64>>>(1);
    k_conv  <<<4000, 256>>>(c2w, c2b);
    k_lif4  <<<1, 32>>>();
    k_fcskip<<<2000, 256>>>(f2w, f2b, s2w, s2b, 1);
    k_liff  <<<1, 1024>>>();
    k_fused <<<512, 32>>>();
    k_stats <<<1, 32>>>(gam, bet);
    k_logits<<<512, 32>>>(clw, clb, out);
}